// round 16
// baseline (speedup 1.0000x reference)
#include <cuda_runtime.h>
#include <cuda_bf16.h>
#include <math.h>
#include <cstdint>
#include <cstddef>

#define T_DIM 512
#define B_DIM 128
#define D_DIM 256
#define H_DIM 512

typedef unsigned long long u64;

// Scratch for precomputed input projection (+ biases). __device__ global =
// the sanctioned allocation-free scratch mechanism.
__device__ float g_xin[(size_t)T_DIM * B_DIM * H_DIM];

__device__ __forceinline__ uint32_t smem_u32(const void *p) {
    uint32_t a;
    asm("{ .reg .u64 t; cvta.to.shared.u64 t, %1; cvt.u32.u64 %0, t; }" : "=r"(a) : "l"(p));
    return a;
}
__device__ __forceinline__ uint32_t mapa_u32(uint32_t addr, uint32_t rank) {
    uint32_t r;
    asm("mapa.shared::cluster.u32 %0, %1, %2;" : "=r"(r) : "r"(addr), "r"(rank));
    return r;
}
__device__ __forceinline__ void mbar_init(uint32_t a, uint32_t cnt) {
    asm volatile("mbarrier.init.shared.b64 [%0], %1;" :: "r"(a), "r"(cnt) : "memory");
}
__device__ __forceinline__ void mbar_expect_tx(uint32_t a, uint32_t tx) {
    asm volatile("mbarrier.arrive.expect_tx.shared.b64 _, [%0], %1;" :: "r"(a), "r"(tx) : "memory");
}
// BOUNDED wait with SUSPEND-HINT try_wait: each retry HW-sleeps the warp
// until wakeup (no busy-poll issue traffic / smem-port hammering). Gives up
// after 4096 sleeps on protocol failure instead of hanging the GPU.
__device__ __forceinline__ void mbar_wait(uint32_t a, uint32_t parity) {
    uint32_t done = 0;
#pragma unroll 1
    for (int i = 0; i < 4096 && !done; i++) {
        asm volatile(
            "{\n\t.reg .pred p;\n\t"
            "mbarrier.try_wait.parity.acquire.cta.shared::cta.b64 p, [%1], %2, 0x989680;\n\t"
            "selp.b32 %0, 1, 0, p;\n\t}"
            : "=r"(done) : "r"(a), "r"(parity) : "memory");
    }
}
__device__ __forceinline__ void dsmem_bulk(uint32_t dst_cluster, uint32_t src_cta,
                                           uint32_t bytes, uint32_t mbar_cluster) {
    asm volatile(
        "cp.async.bulk.shared::cluster.shared::cta.mbarrier::complete_tx::bytes "
        "[%0], [%1], %2, [%3];"
        :: "r"(dst_cluster), "r"(src_cta), "r"(bytes), "r"(mbar_cluster) : "memory");
}
#define FENCE_ASYNC() asm volatile("fence.proxy.async.shared::cta;" ::: "memory")

// mma.sync m16n8k16 bf16 (sm_80+ baseline -> compiles for plain sm_100).
__device__ __forceinline__ void hmma(float *c, const uint32_t *a, uint32_t b0, uint32_t b1) {
    asm volatile(
        "mma.sync.aligned.m16n8k16.row.col.f32.bf16.bf16.f32 "
        "{%0,%1,%2,%3}, {%4,%5,%6,%7}, {%8,%9}, {%0,%1,%2,%3};"
        : "+f"(c[0]), "+f"(c[1]), "+f"(c[2]), "+f"(c[3])
        : "r"(a[0]), "r"(a[1]), "r"(a[2]), "r"(a[3]), "r"(b0), "r"(b1));
}
__device__ __forceinline__ void ldsm2t(uint32_t &b0, uint32_t &b1, uint32_t addr) {
    asm volatile("ldmatrix.sync.aligned.m8n8.x2.trans.shared.b16 {%0,%1}, [%2];"
                 : "=r"(b0), "=r"(b1) : "r"(addr));
}
__device__ __forceinline__ void split_pack(float2 v, uint32_t &hi, uint32_t &lo) {
    const __nv_bfloat16 h0 = __float2bfloat16_rn(v.x);
    const __nv_bfloat16 h1 = __float2bfloat16_rn(v.y);
    const __nv_bfloat16 l0 = __float2bfloat16_rn(v.x - __bfloat162float(h0));
    const __nv_bfloat16 l1 = __float2bfloat16_rn(v.y - __bfloat162float(h1));
    hi = (uint32_t)*reinterpret_cast<const uint16_t *>(&h0)
       | ((uint32_t)*reinterpret_cast<const uint16_t *>(&h1) << 16);
    lo = (uint32_t)*reinterpret_cast<const uint16_t *>(&l0)
       | ((uint32_t)*reinterpret_cast<const uint16_t *>(&l1) << 16);
}
__device__ __forceinline__ void split1(float v, __nv_bfloat16 &hi, __nv_bfloat16 &lo) {
    hi = __float2bfloat16_rn(v);
    lo = __float2bfloat16_rn(v - __bfloat162float(hi));
}
__device__ __forceinline__ float tanh_fast(float s) {
    float e = __expf(2.0f * s);
    return 1.0f - __fdividef(2.0f, e + 1.0f);
}

// ---------------------------------------------------------------------------
// Kernel 1: xin via HMMA — one CTA per 64-tb stripe, all 512 n, 8 n-chunks.
// R14 structure, plus register relief: the 8 accumulator groups are processed
// in TWO blocks of 4 (acc 32 -> 16 regs) to kill spills under the 128-reg
// budget of launch_bounds(256,2).
//
// smem: xs hi [0,32768), xs lo [32768,65536), Dsm [65536,102400)
// ---------------------------------------------------------------------------
#define XIN_SMEM 102400

__global__ void __launch_bounds__(256, 2)
xin_hmma(const float *__restrict__ x, const float *__restrict__ W_in,
         const float *__restrict__ b_in, const float *__restrict__ b_lat) {
    extern __shared__ char smem[];
    const uint32_t xb = smem_u32(smem);
    float *Dsm = reinterpret_cast<float *>(smem + 65536);

    const int tid = threadIdx.x;
    const int lane = tid & 31;
    const int w = tid >> 5;
    const int mt = w >> 1;          // 16-n tile within chunk
    const int kh = w & 1;           // interleaved k half
    const int gb = blockIdx.x;      // tb-block of 64

    const int fg = lane >> 2;
    const int fc = (lane & 3) * 2;
    const uint32_t lrow16 = (uint32_t)(lane & 15) * 16;

    // ---- stage ALL 64 x rows ONCE: thread = k, pair-packed 4B stores ----
    {
        const int k = tid;
        const float *xrow = x + (size_t)(gb * 64) * D_DIM + k;
#pragma unroll 4
        for (int g = 0; g < 8; g++) {
#pragma unroll
            for (int tp = 0; tp < 4; tp++) {
                const float v0 = xrow[(size_t)(g * 8 + tp * 2) * D_DIM];
                const float v1 = xrow[(size_t)(g * 8 + tp * 2 + 1) * D_DIM];
                uint32_t hi, lo;
                split_pack(make_float2(v0, v1), hi, lo);
                *reinterpret_cast<uint32_t *>(smem + g * 4096 + k * 16 + tp * 4) = hi;
                *reinterpret_cast<uint32_t *>(smem + 32768 + g * 4096 + k * 16 + tp * 4) = lo;
            }
        }
    }
    __syncthreads();

    const int bE = w;            // tb within group (epilogue)
    const int jE = lane * 2;     // n offset within chunk (epilogue)

#pragma unroll 1
    for (int nc = 0; nc < 8; nc++) {
        const int n0 = nc * 64;

        // ---- W_in A-fragments for this n-chunk (hi/lo split, from L2) ----
        uint32_t whi[8][4], wlo[8][4];
        {
            const int r0 = n0 + mt * 16 + fg;
            const int r1 = r0 + 8;
#pragma unroll
            for (int li = 0; li < 8; li++) {
                const int q = 2 * li + kh;
                const int kb = q * 16 + fc;
                float2 v;
                v = *reinterpret_cast<const float2 *>(&W_in[(size_t)r0 * D_DIM + kb]);
                split_pack(v, whi[li][0], wlo[li][0]);
                v = *reinterpret_cast<const float2 *>(&W_in[(size_t)r1 * D_DIM + kb]);
                split_pack(v, whi[li][1], wlo[li][1]);
                v = *reinterpret_cast<const float2 *>(&W_in[(size_t)r0 * D_DIM + kb + 8]);
                split_pack(v, whi[li][2], wlo[li][2]);
                v = *reinterpret_cast<const float2 *>(&W_in[(size_t)r1 * D_DIM + kb + 8]);
                split_pack(v, whi[li][3], wlo[li][3]);
            }
        }

        // ---- GEMM in TWO blocks of 4 groups (acc regs 32 -> 16) ----
#pragma unroll
        for (int hb = 0; hb < 2; hb++) {
            float acc[4][4];
#pragma unroll
            for (int g = 0; g < 4; g++)
#pragma unroll
                for (int i = 0; i < 4; i++) acc[g][i] = 0.f;

#pragma unroll
            for (int li = 0; li < 8; li++) {
                const int q = 2 * li + kh;
#pragma unroll
                for (int g = 0; g < 4; g++) {
                    const int gg = hb * 4 + g;
                    const uint32_t addr = xb + (uint32_t)gg * 4096 + (uint32_t)q * 256 + lrow16;
                    uint32_t bh0, bh1, bl0, bl1;
                    ldsm2t(bh0, bh1, addr);
                    ldsm2t(bl0, bl1, addr + 32768u);
                    hmma(acc[g], whi[li], bh0, bh1);
                    hmma(acc[g], wlo[li], bh0, bh1);
                    hmma(acc[g], whi[li], bl0, bl1);
                }
            }
#pragma unroll
            for (int g = 0; g < 4; g++) {
                const int gg = hb * 4 + g;
                float *d0 = Dsm + (kh * 8 + gg) * 576 + fc * 72 + mt * 16 + fg;
                d0[0] = acc[g][0]; d0[72] = acc[g][1]; d0[8] = acc[g][2]; d0[80] = acc[g][3];
            }
        }
        __syncthreads();

        // ---- epilogue: bias + write, 2 floats x 8 groups per thread ----
        const float2 bias = make_float2(b_in[n0 + jE] + b_lat[n0 + jE],
                                        b_in[n0 + jE + 1] + b_lat[n0 + jE + 1]);
#pragma unroll
        for (int g = 0; g < 8; g++) {
            const float2 a0 = *reinterpret_cast<const float2 *>(&Dsm[g * 576 + bE * 72 + jE]);
            const float2 a1 = *reinterpret_cast<const float2 *>(&Dsm[(8 + g) * 576 + bE * 72 + jE]);
            float2 o = make_float2(a0.x + a1.x + bias.x, a0.y + a1.y + bias.y);
            *reinterpret_cast<float2 *>(
                &g_xin[(size_t)(gb * 64 + g * 8 + bE) * H_DIM + n0 + jE]) = o;
        }
        __syncthreads();   // Dsm WAR before next chunk
    }
}

// ---------------------------------------------------------------------------
// Kernel 2: HMMA scan — R12/R14 structure byte-for-byte; ONLY change is the
// sleeping (suspend-hint) mbar_wait above.
//
// smem bytes:
//   [0,32)        mbars: b0A@0 b0B@8 b1A@16 b1B@24
//   [64,32832)    hbuf: 2 bufs x 8 ranks x {hi 1KB, lo 1KB}
//   [32832,42048) Dsm: 4 quarters x 8 x 72 floats
// ---------------------------------------------------------------------------
#define MB_OFF     0
#define HBUF_OFF   64
#define BUF_STRIDE 16384
#define DSM_OFF    32832
#define SMEM_SCAN_BYTES 42112

__global__ void __cluster_dims__(8, 1, 1) __launch_bounds__(512, 1)
rnn_scan(const float *__restrict__ h0, const float *__restrict__ W_lat,
         float *__restrict__ out) {
    extern __shared__ char smem[];
    const uint32_t sbase = smem_u32(smem);
    float *Dsm = reinterpret_cast<float *>(smem + DSM_OFF);

    const int tid = threadIdx.x;
    const int lane = tid & 31;
    const int w = tid >> 5;
    const int mt = w >> 2;        // M-tile (16 j rows), 0..3
    const int kq = w & 3;         // k-quarter (128 k = 8 ktiles)
    const int r = blockIdx.x & 7;
    const int g = blockIdx.x >> 3;
    const int j0g = r * 64;
    const int b0 = g * 8;

    if (tid < 4) mbar_init(sbase + MB_OFF + tid * 8, 1);

    // ---- W A-fragments into registers (hi/lo split), one-time ----
    const int fg = lane >> 2;
    const int fc = (lane & 3) * 2;
    uint32_t whi[8][4], wlo[8][4];
    {
        const int r0 = j0g + mt * 16 + fg;
        const int r1 = r0 + 8;
#pragma unroll
        for (int q = 0; q < 8; q++) {
            const int kb = kq * 128 + q * 16 + fc;
            float2 v;
            v = *reinterpret_cast<const float2 *>(&W_lat[(size_t)r0 * H_DIM + kb]);
            split_pack(v, whi[q][0], wlo[q][0]);
            v = *reinterpret_cast<const float2 *>(&W_lat[(size_t)r1 * H_DIM + kb]);
            split_pack(v, whi[q][1], wlo[q][1]);
            v = *reinterpret_cast<const float2 *>(&W_lat[(size_t)r0 * H_DIM + kb + 8]);
            split_pack(v, whi[q][2], wlo[q][2]);
            v = *reinterpret_cast<const float2 *>(&W_lat[(size_t)r1 * H_DIM + kb + 8]);
            split_pack(v, whi[q][3], wlo[q][3]);
        }
    }

    // ---- preload h(-1) = h0 into buf 1 ----
    for (int i = tid; i < 8 * 512; i += 512) {
        const int b = i & 7, k = i >> 3;
        const float hv = h0[(size_t)(b0 + b) * H_DIM + k];
        __nv_bfloat16 hi, lo;
        split1(hv, hi, lo);
        char *base = smem + HBUF_OFF + BUF_STRIDE + (k >> 6) * 2048 + (k & 63) * 16 + b * 2;
        *reinterpret_cast<__nv_bfloat16 *>(base) = hi;
        *reinterpret_cast<__nv_bfloat16 *>(base + 1024) = lo;
    }
    __syncthreads();
    // Expects for h(0) (lands in buf0) BEFORE any peer can send it.
    if (tid == 0) {
        mbar_expect_tx(sbase + MB_OFF + 0, 7 * 1024u);   // buf0 hi
        mbar_expect_tx(sbase + MB_OFF + 8, 7 * 1024u);   // buf0 lo
    }
    asm volatile("barrier.cluster.arrive.aligned;" ::: "memory");
    asm volatile("barrier.cluster.wait.aligned;" ::: "memory");

    // Epilogue mapping: 1 output/thread: b = tid>>6, j = tid&63.
    const int bE = tid >> 6;
    const int jE = tid & 63;
    float *const out_base = out + (size_t)(b0 + bE) * H_DIM + j0g + jE;
    const float *const xin_b = g_xin + (size_t)(b0 + bE) * H_DIM + j0g + jE;

    const uint32_t lrow16 = (uint32_t)(lane & 15) * 16;
    int parA[2] = {0, 0}, parB[2] = {0, 0};

    float xpre = __ldcg(xin_b);

    for (int t = 0; t < T_DIM; t++) {
        float xnext = 0.f;
        if (t + 1 < T_DIM)
            xnext = __ldcg(xin_b + (size_t)(t + 1) * B_DIM * H_DIM);

        const int rb = (t - 1) & 1;   // buffer with h(t-1); t=0 -> preloaded buf1
        const uint32_t hbq = sbase + HBUF_OFF + (uint32_t)rb * BUF_STRIDE
                           + (uint32_t)kq * 4096u;

        float acc[4][4];
#pragma unroll
        for (int i = 0; i < 4; i++)
#pragma unroll
            for (int j = 0; j < 4; j++) acc[i][j] = 0.f;

        // ---- pass 1: hi operand (wait hi group) ----
        if (t > 0) { mbar_wait(sbase + MB_OFF + rb * 16 + 0, parA[rb]); parA[rb] ^= 1; }
#pragma unroll
        for (int q = 0; q < 8; q++) {
            const uint32_t addr = hbq + (uint32_t)(q >> 2) * 2048
                                + (uint32_t)(q & 3) * 256 + lrow16;
            uint32_t bh0, bh1;
            ldsm2t(bh0, bh1, addr);
            hmma(acc[0], whi[q], bh0, bh1);
            hmma(acc[1], wlo[q], bh0, bh1);
        }
        // ---- pass 2: lo operand (wait lo group; hides behind pass 1) ----
        if (t > 0) { mbar_wait(sbase + MB_OFF + rb * 16 + 8, parB[rb]); parB[rb] ^= 1; }
#pragma unroll
        for (int q = 0; q < 8; q++) {
            const uint32_t addr = hbq + (uint32_t)(q >> 2) * 2048
                                + (uint32_t)(q & 3) * 256 + lrow16 + 1024u;
            uint32_t bl0, bl1;
            ldsm2t(bl0, bl1, addr);
            hmma(acc[2], whi[q], bl0, bl1);
            hmma(acc[3], wlo[q], bl0, bl1);
        }

        float c4[4];
#pragma unroll
        for (int i = 0; i < 4; i++)
            c4[i] = (acc[0][i] + acc[1][i]) + (acc[2][i] + acc[3][i]);

        // ---- reduce: kq quarters -> disjoint Dsm quarters, ONE sync ----
        {
            float *d0 = Dsm + kq * 576 + fc * 72 + mt * 16 + fg;
            d0[0] = c4[0]; d0[72] = c4[1]; d0[8] = c4[2]; d0[80] = c4[3];
        }
        __syncthreads();

        // ---- epilogue: 1 output per thread ----
        const int di = bE * 72 + jE;
        const float s = (Dsm[di] + Dsm[576 + di])
                      + (Dsm[1152 + di] + Dsm[1728 + di]) + xpre;
        const float res = tanh_fast(s);
        __stcg(out_base + (size_t)t * B_DIM * H_DIM, res);
        xpre = xnext;

        // Expects for h(t+1) BEFORE sending h(t).
        if (tid == 0 && t + 1 < T_DIM) {
            mbar_expect_tx(sbase + MB_OFF + ((t + 1) & 1) * 16 + 0, 7 * 1024u);
            mbar_expect_tx(sbase + MB_OFF + ((t + 1) & 1) * 16 + 8, 7 * 1024u);
        }

        if (t < T_DIM - 1) {
            // Stage own slice into buf(t&1) rank-r block, [k][b] layout.
            __nv_bfloat16 hi, lo;
            split1(res, hi, lo);
            char *bb = smem + HBUF_OFF + (t & 1) * BUF_STRIDE + r * 2048;
            *reinterpret_cast<__nv_bfloat16 *>(bb + jE * 16 + bE * 2) = hi;
            *reinterpret_cast<__nv_bfloat16 *>(bb + 1024 + jE * 16 + bE * 2) = lo;
            FENCE_ASYNC();
            __syncthreads();
            if (tid < 14) {
                // lanes 0-6: hi slices (drain first); lanes 7-13: lo slices.
                const int sel = (tid < 7) ? 0 : 1;
                const int pi  = (tid < 7) ? tid : (tid - 7);
                const uint32_t peer = (uint32_t)((r + 1 + pi) & 7);
                const uint32_t src = sbase + HBUF_OFF + (t & 1) * BUF_STRIDE
                                   + r * 2048 + (uint32_t)sel * 1024u;
                const uint32_t mb = sbase + MB_OFF + (t & 1) * 16 + (uint32_t)sel * 8u;
                dsmem_bulk(mapa_u32(src, peer), src, 1024u, mapa_u32(mb, peer));
            }
        }
    }

    asm volatile("barrier.cluster.arrive.aligned;" ::: "memory");
    asm volatile("barrier.cluster.wait.aligned;" ::: "memory");
}

// ---------------------------------------------------------------------------
extern "C" void kernel_launch(void *const *d_in, const int *in_sizes, int n_in,
                              void *d_out, int out_size) {
    const float *x     = (const float *)d_in[0];
    const float *h     = (const float *)d_in[1];
    const float *W_in  = (const float *)d_in[2];
    const float *b_in  = (const float *)d_in[3];
    const float *W_lat = (const float *)d_in[4];
    const float *b_lat = (const float *)d_in[5];
    float *out = (float *)d_out;

    cudaFuncSetAttribute(xin_hmma, cudaFuncAttributeMaxDynamicSharedMemorySize,
                         XIN_SMEM);
    xin_hmma<<<1024, 256, XIN_SMEM>>>(x, W_in, b_in, b_lat);

    cudaFuncSetAttribute(rnn_scan, cudaFuncAttributeMaxDynamicSharedMemorySize,
                         SMEM_SCAN_BYTES);
    rnn_scan<<<B_DIM, 512, SMEM_SCAN_BYTES>>>(h, W_lat, out);
}

// round 17
// speedup vs baseline: 1.0764x; 1.0764x over previous
#include <cuda_runtime.h>
#include <cuda_bf16.h>
#include <math.h>
#include <cstdint>
#include <cstddef>

#define T_DIM 512
#define B_DIM 128
#define D_DIM 256
#define H_DIM 512

typedef unsigned long long u64;

// Scratch for precomputed input projection (+ biases). __device__ global =
// the sanctioned allocation-free scratch mechanism.
__device__ float g_xin[(size_t)T_DIM * B_DIM * H_DIM];

__device__ __forceinline__ uint32_t smem_u32(const void *p) {
    uint32_t a;
    asm("{ .reg .u64 t; cvta.to.shared.u64 t, %1; cvt.u32.u64 %0, t; }" : "=r"(a) : "l"(p));
    return a;
}
__device__ __forceinline__ uint32_t mapa_u32(uint32_t addr, uint32_t rank) {
    uint32_t r;
    asm("mapa.shared::cluster.u32 %0, %1, %2;" : "=r"(r) : "r"(addr), "r"(rank));
    return r;
}
__device__ __forceinline__ void mbar_init(uint32_t a, uint32_t cnt) {
    asm volatile("mbarrier.init.shared.b64 [%0], %1;" :: "r"(a), "r"(cnt) : "memory");
}
__device__ __forceinline__ void mbar_expect_tx(uint32_t a, uint32_t tx) {
    asm volatile("mbarrier.arrive.expect_tx.shared.b64 _, [%0], %1;" :: "r"(a), "r"(tx) : "memory");
}
// BOUNDED wait with suspend-hint try_wait (HW sleep per retry; bounded so a
// protocol bug gives a fast wrong answer instead of a dead container).
__device__ __forceinline__ void mbar_wait(uint32_t a, uint32_t parity) {
    uint32_t done = 0;
#pragma unroll 1
    for (int i = 0; i < 4096 && !done; i++) {
        asm volatile(
            "{\n\t.reg .pred p;\n\t"
            "mbarrier.try_wait.parity.acquire.cta.shared::cta.b64 p, [%1], %2, 0x989680;\n\t"
            "selp.b32 %0, 1, 0, p;\n\t}"
            : "=r"(done) : "r"(a), "r"(parity) : "memory");
    }
}
__device__ __forceinline__ void dsmem_bulk(uint32_t dst_cluster, uint32_t src_cta,
                                           uint32_t bytes, uint32_t mbar_cluster) {
    asm volatile(
        "cp.async.bulk.shared::cluster.shared::cta.mbarrier::complete_tx::bytes "
        "[%0], [%1], %2, [%3];"
        :: "r"(dst_cluster), "r"(src_cta), "r"(bytes), "r"(mbar_cluster) : "memory");
}
#define FENCE_ASYNC() asm volatile("fence.proxy.async.shared::cta;" ::: "memory")

// mma.sync m16n8k16 bf16 (sm_80+ baseline -> compiles for plain sm_100).
__device__ __forceinline__ void hmma(float *c, const uint32_t *a, uint32_t b0, uint32_t b1) {
    asm volatile(
        "mma.sync.aligned.m16n8k16.row.col.f32.bf16.bf16.f32 "
        "{%0,%1,%2,%3}, {%4,%5,%6,%7}, {%8,%9}, {%0,%1,%2,%3};"
        : "+f"(c[0]), "+f"(c[1]), "+f"(c[2]), "+f"(c[3])
        : "r"(a[0]), "r"(a[1]), "r"(a[2]), "r"(a[3]), "r"(b0), "r"(b1));
}
__device__ __forceinline__ void ldsm2t(uint32_t &b0, uint32_t &b1, uint32_t addr) {
    asm volatile("ldmatrix.sync.aligned.m8n8.x2.trans.shared.b16 {%0,%1}, [%2];"
                 : "=r"(b0), "=r"(b1) : "r"(addr));
}
__device__ __forceinline__ void split_pack(float2 v, uint32_t &hi, uint32_t &lo) {
    const __nv_bfloat16 h0 = __float2bfloat16_rn(v.x);
    const __nv_bfloat16 h1 = __float2bfloat16_rn(v.y);
    const __nv_bfloat16 l0 = __float2bfloat16_rn(v.x - __bfloat162float(h0));
    const __nv_bfloat16 l1 = __float2bfloat16_rn(v.y - __bfloat162float(h1));
    hi = (uint32_t)*reinterpret_cast<const uint16_t *>(&h0)
       | ((uint32_t)*reinterpret_cast<const uint16_t *>(&h1) << 16);
    lo = (uint32_t)*reinterpret_cast<const uint16_t *>(&l0)
       | ((uint32_t)*reinterpret_cast<const uint16_t *>(&l1) << 16);
}
__device__ __forceinline__ void split1(float v, __nv_bfloat16 &hi, __nv_bfloat16 &lo) {
    hi = __float2bfloat16_rn(v);
    lo = __float2bfloat16_rn(v - __bfloat162float(hi));
}
__device__ __forceinline__ float tanh_fast(float s) {
    float e = __expf(2.0f * s);
    return 1.0f - __fdividef(2.0f, e + 1.0f);
}

// ---------------------------------------------------------------------------
// Kernel 1: xin via HMMA — byte-for-byte R14 (best measured config, ~190us).
// One CTA per 64-tb stripe, all 512 n, 8 n-chunks; launch_bounds(256,2).
// smem: xs hi [0,32768), xs lo [32768,65536), Dsm [65536,102400)
// ---------------------------------------------------------------------------
#define XIN_SMEM 102400

__global__ void __launch_bounds__(256, 2)
xin_hmma(const float *__restrict__ x, const float *__restrict__ W_in,
         const float *__restrict__ b_in, const float *__restrict__ b_lat) {
    extern __shared__ char smem[];
    const uint32_t xb = smem_u32(smem);
    float *Dsm = reinterpret_cast<float *>(smem + 65536);

    const int tid = threadIdx.x;
    const int lane = tid & 31;
    const int w = tid >> 5;
    const int mt = w >> 1;
    const int kh = w & 1;
    const int gb = blockIdx.x;

    const int fg = lane >> 2;
    const int fc = (lane & 3) * 2;
    const uint32_t lrow16 = (uint32_t)(lane & 15) * 16;

    // ---- stage ALL 64 x rows ONCE ----
    {
        const int k = tid;
        const float *xrow = x + (size_t)(gb * 64) * D_DIM + k;
#pragma unroll 4
        for (int g = 0; g < 8; g++) {
#pragma unroll
            for (int tp = 0; tp < 4; tp++) {
                const float v0 = xrow[(size_t)(g * 8 + tp * 2) * D_DIM];
                const float v1 = xrow[(size_t)(g * 8 + tp * 2 + 1) * D_DIM];
                uint32_t hi, lo;
                split_pack(make_float2(v0, v1), hi, lo);
                *reinterpret_cast<uint32_t *>(smem + g * 4096 + k * 16 + tp * 4) = hi;
                *reinterpret_cast<uint32_t *>(smem + 32768 + g * 4096 + k * 16 + tp * 4) = lo;
            }
        }
    }
    __syncthreads();

    const int bE = w;
    const int jE = lane * 2;

#pragma unroll 1
    for (int nc = 0; nc < 8; nc++) {
        const int n0 = nc * 64;

        uint32_t whi[8][4], wlo[8][4];
        {
            const int r0 = n0 + mt * 16 + fg;
            const int r1 = r0 + 8;
#pragma unroll
            for (int li = 0; li < 8; li++) {
                const int q = 2 * li + kh;
                const int kb = q * 16 + fc;
                float2 v;
                v = *reinterpret_cast<const float2 *>(&W_in[(size_t)r0 * D_DIM + kb]);
                split_pack(v, whi[li][0], wlo[li][0]);
                v = *reinterpret_cast<const float2 *>(&W_in[(size_t)r1 * D_DIM + kb]);
                split_pack(v, whi[li][1], wlo[li][1]);
                v = *reinterpret_cast<const float2 *>(&W_in[(size_t)r0 * D_DIM + kb + 8]);
                split_pack(v, whi[li][2], wlo[li][2]);
                v = *reinterpret_cast<const float2 *>(&W_in[(size_t)r1 * D_DIM + kb + 8]);
                split_pack(v, whi[li][3], wlo[li][3]);
            }
        }

        float acc[8][4];
#pragma unroll
        for (int g = 0; g < 8; g++)
#pragma unroll
            for (int i = 0; i < 4; i++) acc[g][i] = 0.f;

#pragma unroll
        for (int li = 0; li < 8; li++) {
            const int q = 2 * li + kh;
#pragma unroll
            for (int g = 0; g < 8; g++) {
                const uint32_t addr = xb + (uint32_t)g * 4096 + (uint32_t)q * 256 + lrow16;
                uint32_t bh0, bh1, bl0, bl1;
                ldsm2t(bh0, bh1, addr);
                ldsm2t(bl0, bl1, addr + 32768u);
                hmma(acc[g], whi[li], bh0, bh1);
                hmma(acc[g], wlo[li], bh0, bh1);
                hmma(acc[g], whi[li], bl0, bl1);
            }
        }

#pragma unroll
        for (int g = 0; g < 8; g++) {
            float *d0 = Dsm + (kh * 8 + g) * 576 + fc * 72 + mt * 16 + fg;
            d0[0] = acc[g][0]; d0[72] = acc[g][1]; d0[8] = acc[g][2]; d0[80] = acc[g][3];
        }
        __syncthreads();

        const float2 bias = make_float2(b_in[n0 + jE] + b_lat[n0 + jE],
                                        b_in[n0 + jE + 1] + b_lat[n0 + jE + 1]);
#pragma unroll
        for (int g = 0; g < 8; g++) {
            const float2 a0 = *reinterpret_cast<const float2 *>(&Dsm[g * 576 + bE * 72 + jE]);
            const float2 a1 = *reinterpret_cast<const float2 *>(&Dsm[(8 + g) * 576 + bE * 72 + jE]);
            float2 o = make_float2(a0.x + a1.x + bias.x, a0.y + a1.y + bias.y);
            *reinterpret_cast<float2 *>(
                &g_xin[(size_t)(gb * 64 + g * 8 + bE) * H_DIM + n0 + jE]) = o;
        }
        __syncthreads();
    }
}

// ---------------------------------------------------------------------------
// Kernel 2: HMMA scan with PER-KQ mbars + fused single-pass 3-chain GEMM.
// 512 thr / 16 warps: mt = w>>2, kq = w&3 (128-k quarter = rank blocks
// 2kq, 2kq+1). Warp kq only touches those two rank chunks, so it waits on
// its OWN mbar [buf][kq] (tx: 2KB if pair contains own rank, else 4KB) —
// unblocking as soon as its 4KB lands instead of gating on the full 14KB.
// GEMM: one fused pass, 3 parallel 8-deep chains (Whi.hhi + Wlo.hhi +
// Whi.hlo; dropped Wlo.hlo term ~2^-17). Transport identical to R12/R14
// except sends signal peer mbar [buf][r>>1] (hi and lo both).
//
// smem bytes:
//   [0,64)        mbars: [buf(2)][kq(4)] at buf*32 + kq*8
//   [64,32832)    hbuf: 2 bufs x 8 ranks x {hi 1KB, lo 1KB}
//   [32832,42048) Dsm: 4 quarters x 8 x 72 floats
// ---------------------------------------------------------------------------
#define MB_OFF     0
#define HBUF_OFF   64
#define BUF_STRIDE 16384
#define DSM_OFF    32832
#define SMEM_SCAN_BYTES 42112

__global__ void __cluster_dims__(8, 1, 1) __launch_bounds__(512, 1)
rnn_scan(const float *__restrict__ h0, const float *__restrict__ W_lat,
         float *__restrict__ out) {
    extern __shared__ char smem[];
    const uint32_t sbase = smem_u32(smem);
    float *Dsm = reinterpret_cast<float *>(smem + DSM_OFF);

    const int tid = threadIdx.x;
    const int lane = tid & 31;
    const int w = tid >> 5;
    const int mt = w >> 2;        // M-tile (16 j rows), 0..3
    const int kq = w & 3;         // k-quarter (rank blocks 2kq, 2kq+1)
    const int r = blockIdx.x & 7;
    const int g = blockIdx.x >> 3;
    const int j0g = r * 64;
    const int b0 = g * 8;

    if (tid < 8) mbar_init(sbase + MB_OFF + tid * 8, 1);

    // ---- W A-fragments into registers (hi/lo split), one-time ----
    const int fg = lane >> 2;
    const int fc = (lane & 3) * 2;
    uint32_t whi[8][4], wlo[8][4];
    {
        const int r0 = j0g + mt * 16 + fg;
        const int r1 = r0 + 8;
#pragma unroll
        for (int q = 0; q < 8; q++) {
            const int kb = kq * 128 + q * 16 + fc;
            float2 v;
            v = *reinterpret_cast<const float2 *>(&W_lat[(size_t)r0 * H_DIM + kb]);
            split_pack(v, whi[q][0], wlo[q][0]);
            v = *reinterpret_cast<const float2 *>(&W_lat[(size_t)r1 * H_DIM + kb]);
            split_pack(v, whi[q][1], wlo[q][1]);
            v = *reinterpret_cast<const float2 *>(&W_lat[(size_t)r0 * H_DIM + kb + 8]);
            split_pack(v, whi[q][2], wlo[q][2]);
            v = *reinterpret_cast<const float2 *>(&W_lat[(size_t)r1 * H_DIM + kb + 8]);
            split_pack(v, whi[q][3], wlo[q][3]);
        }
    }

    // ---- preload h(-1) = h0 into buf 1 ----
    for (int i = tid; i < 8 * 512; i += 512) {
        const int b = i & 7, k = i >> 3;
        const float hv = h0[(size_t)(b0 + b) * H_DIM + k];
        __nv_bfloat16 hi, lo;
        split1(hv, hi, lo);
        char *base = smem + HBUF_OFF + BUF_STRIDE + (k >> 6) * 2048 + (k & 63) * 16 + b * 2;
        *reinterpret_cast<__nv_bfloat16 *>(base) = hi;
        *reinterpret_cast<__nv_bfloat16 *>(base + 1024) = lo;
    }
    __syncthreads();
    // Expects for h(0) (lands in buf0) BEFORE any peer can send it.
    if (tid == 0) {
#pragma unroll
        for (int q4 = 0; q4 < 4; q4++)
            mbar_expect_tx(sbase + MB_OFF + q4 * 8,
                           (q4 == (r >> 1)) ? 2048u : 4096u);
    }
    asm volatile("barrier.cluster.arrive.aligned;" ::: "memory");
    asm volatile("barrier.cluster.wait.aligned;" ::: "memory");

    // Epilogue mapping: 1 output/thread: b = tid>>6, j = tid&63.
    const int bE = tid >> 6;
    const int jE = tid & 63;
    float *const out_base = out + (size_t)(b0 + bE) * H_DIM + j0g + jE;
    const float *const xin_b = g_xin + (size_t)(b0 + bE) * H_DIM + j0g + jE;

    const uint32_t lrow16 = (uint32_t)(lane & 15) * 16;
    const uint32_t mb_kq = sbase + MB_OFF + (uint32_t)kq * 8;   // + buf*32
    int parQ[2] = {0, 0};

    float xpre = __ldcg(xin_b);

    for (int t = 0; t < T_DIM; t++) {
        float xnext = 0.f;
        if (t + 1 < T_DIM)
            xnext = __ldcg(xin_b + (size_t)(t + 1) * B_DIM * H_DIM);

        const int rb = (t - 1) & 1;   // buffer with h(t-1); t=0 -> preloaded buf1
        const uint32_t hbq = sbase + HBUF_OFF + (uint32_t)rb * BUF_STRIDE
                           + (uint32_t)kq * 4096u;

        // ---- per-warp wait: ONLY this warp's two rank chunks ----
        if (t > 0) { mbar_wait(mb_kq + rb * 32, parQ[rb]); parQ[rb] ^= 1; }

        // ---- fused GEMM: 8 ktiles x 3 parallel chains ----
        float acc[3][4];
#pragma unroll
        for (int i = 0; i < 3; i++)
#pragma unroll
            for (int j = 0; j < 4; j++) acc[i][j] = 0.f;

#pragma unroll
        for (int q = 0; q < 8; q++) {
            const uint32_t addr = hbq + (uint32_t)(q >> 2) * 2048
                                + (uint32_t)(q & 3) * 256 + lrow16;
            uint32_t bh0, bh1, bl0, bl1;
            ldsm2t(bh0, bh1, addr);
            ldsm2t(bl0, bl1, addr + 1024u);
            hmma(acc[0], whi[q], bh0, bh1);
            hmma(acc[1], wlo[q], bh0, bh1);
            hmma(acc[2], whi[q], bl0, bl1);
        }

        float c4[4];
#pragma unroll
        for (int i = 0; i < 4; i++)
            c4[i] = acc[0][i] + acc[1][i] + acc[2][i];

        // ---- reduce: kq quarters -> disjoint Dsm quarters, ONE sync ----
        {
            float *d0 = Dsm + kq * 576 + fc * 72 + mt * 16 + fg;
            d0[0] = c4[0]; d0[72] = c4[1]; d0[8] = c4[2]; d0[80] = c4[3];
        }
        __syncthreads();

        // ---- epilogue: 1 output per thread ----
        const int di = bE * 72 + jE;
        const float s = (Dsm[di] + Dsm[576 + di])
                      + (Dsm[1152 + di] + Dsm[1728 + di]) + xpre;
        const float res = tanh_fast(s);
        __stcg(out_base + (size_t)t * B_DIM * H_DIM, res);
        xpre = xnext;

        // Expects for h(t+1) BEFORE sending h(t): a peer sends h(t+1) only
        // after receiving our h(t), which follows our sends below.
        if (tid == 0 && t + 1 < T_DIM) {
            const uint32_t nb = (uint32_t)((t + 1) & 1) * 32;
#pragma unroll
            for (int q4 = 0; q4 < 4; q4++)
                mbar_expect_tx(sbase + MB_OFF + nb + q4 * 8,
                               (q4 == (r >> 1)) ? 2048u : 4096u);
        }

        if (t < T_DIM - 1) {
            // Stage own slice into buf(t&1) rank-r block, [k][b] layout.
            __nv_bfloat16 hi, lo;
            split1(res, hi, lo);
            char *bb = smem + HBUF_OFF + (t & 1) * BUF_STRIDE + r * 2048;
            *reinterpret_cast<__nv_bfloat16 *>(bb + jE * 16 + bE * 2) = hi;
            *reinterpret_cast<__nv_bfloat16 *>(bb + 1024 + jE * 16 + bE * 2) = lo;
            FENCE_ASYNC();
            __syncthreads();
            if (tid < 14) {
                // lanes 0-6: hi slices; lanes 7-13: lo slices. Both signal the
                // peer's mbar [buf][r>>1] (our chunk index = our rank).
                const int sel = (tid < 7) ? 0 : 1;
                const int pi  = (tid < 7) ? tid : (tid - 7);
                const uint32_t peer = (uint32_t)((r + 1 + pi) & 7);
                const uint32_t src = sbase + HBUF_OFF + (t & 1) * BUF_STRIDE
                                   + r * 2048 + (uint32_t)sel * 1024u;
                const uint32_t mb = sbase + MB_OFF + (t & 1) * 32 + (uint32_t)(r >> 1) * 8;
                dsmem_bulk(mapa_u32(src, peer), src, 1024u, mapa_u32(mb, peer));
            }
        }
    }

    asm volatile("barrier.cluster.arrive.aligned;" ::: "memory");
    asm volatile("barrier.cluster.wait.aligned;" ::: "memory");
}

// ---------------------------------------------------------------------------
extern "C" void kernel_launch(void *const *d_in, const int *in_sizes, int n_in,
                              void *d_out, int out_size) {
    const float *x     = (const float *)d_in[0];
    const float *h     = (const float *)d_in[1];
    const float *W_in  = (const float *)d_in[2];
    const float *b_in  = (const float *)d_in[3];
    const float *W_lat = (const float *)d_in[4];
    const float *b_lat = (const float *)d_in[5];
    float *out = (float *)d_out;

    cudaFuncSetAttribute(xin_hmma, cudaFuncAttributeMaxDynamicSharedMemorySize,
                         XIN_SMEM);
    xin_hmma<<<1024, 256, XIN_SMEM>>>(x, W_in, b_in, b_lat);

    cudaFuncSetAttribute(rnn_scan, cudaFuncAttributeMaxDynamicSharedMemorySize,
                         SMEM_SCAN_BYTES);
    rnn_scan<<<B_DIM, 512, SMEM_SCAN_BYTES>>>(h, W_lat, out);
}